// round 1
// baseline (speedup 1.0000x reference)
#include <cuda_runtime.h>

// Problem constants
#define BATCH   4096
#define NU      20      // DIM_U1 == DIM_U2
#define DZ      6
#define NCOL    120     // DZ * DIM_U2

// Output region offsets (floats) in d_out: f1 | g1 | f2 | g2
#define F1OFF   0
#define G1OFF   (BATCH * NU)                       // 81920
#define F2OFF   (G1OFF + BATCH * NU * NCOL)        // 9912320
#define G2OFF   (F2OFF + BATCH * NCOL)             // 10403840

// Shared-memory float offsets
#define W1A 0
#define B1A 48
#define W1B 64
#define B1B 576
#define W1C 608
#define B1C 1120
#define W1D 1136
#define B1D 1440
#define W2A 1459
#define B2A 1507
#define W2B 1523
#define B2B 2035
#define W2C 2067
#define B2C 2579
#define W2D 2595
#define B2D 5571
#define SX  5757          // x row, 20 floats
// slot X: hA (phase A out) then reused as hC (phase C out)
#define HA1 5777          // 20*16
#define HA2 6097          // 20*16
#define HC1 5777
#define HC2 6097
// slot Y: hB (phase B out) then reused as out1/out2 (phase D out)
#define HB1 6417          // 20*32
#define HB2 7057          // 20*32
#define OUT1 6417         // 20*19 = 380
#define OUT2 6797         // 20*186 = 3720  (ends 10517)
#define SMEM_FLOATS 10537

__global__ __launch_bounds__(256) void CGN_fused_kernel(
    const float* __restrict__ x,
    const float* __restrict__ w1a, const float* __restrict__ bb1a,
    const float* __restrict__ w1b, const float* __restrict__ bb1b,
    const float* __restrict__ w1c, const float* __restrict__ bb1c,
    const float* __restrict__ w1d, const float* __restrict__ bb1d,
    const float* __restrict__ w2a, const float* __restrict__ bb2a,
    const float* __restrict__ w2b, const float* __restrict__ bb2b,
    const float* __restrict__ w2c, const float* __restrict__ bb2c,
    const float* __restrict__ w2d, const float* __restrict__ bb2d,
    float* __restrict__ out)
{
    __shared__ float sm[SMEM_FLOATS];
    const int tid = threadIdx.x;
    const int b   = blockIdx.x;

    // ---- stage weights + x row into smem ----
    #define CP(off, src, n) for (int i = tid; i < (n); i += 256) sm[(off) + i] = (src)[i];
    CP(W1A, w1a, 48)   CP(B1A, bb1a, 16)
    CP(W1B, w1b, 512)  CP(B1B, bb1b, 32)
    CP(W1C, w1c, 512)  CP(B1C, bb1c, 16)
    CP(W1D, w1d, 304)  CP(B1D, bb1d, 19)
    CP(W2A, w2a, 48)   CP(B2A, bb2a, 16)
    CP(W2B, w2b, 512)  CP(B2B, bb2b, 32)
    CP(W2C, w2c, 512)  CP(B2C, bb2c, 16)
    CP(W2D, w2d, 2976) CP(B2D, bb2d, 186)
    #undef CP
    for (int i = tid; i < NU; i += 256) sm[SX + i] = x[(size_t)b * NU + i];
    __syncthreads();

    // ---- Phase A: layer a (3 -> 16), both MLPs, all 20 sites. 640 tasks ----
    for (int task = tid; task < 640; task += 256) {
        int site = task >> 5;
        int n    = task & 31;
        float x0 = sm[SX + (site + 19) % NU];
        float x1 = sm[SX + site];
        float x2 = sm[SX + (site + 1) % NU];
        const float *W, *B; int dst;
        if (n < 16) { W = &sm[W1A]; B = &sm[B1A]; dst = HA1 + site * 16 + n; }
        else { n -= 16; W = &sm[W2A]; B = &sm[B2A]; dst = HA2 + site * 16 + n; }
        float acc = B[n] + x0 * W[n] + x1 * W[16 + n] + x2 * W[32 + n];
        sm[dst] = fmaxf(acc, 0.f);
    }
    __syncthreads();

    // ---- Phase B: layer b (16 -> 32). 1280 tasks ----
    for (int task = tid; task < 1280; task += 256) {
        int site = task >> 6;
        int n    = task & 63;
        const float *W, *B, *h; int dst;
        if (n < 32) { W = &sm[W1B]; B = &sm[B1B]; h = &sm[HA1 + site * 16]; dst = HB1 + site * 32 + n; }
        else { n -= 32; W = &sm[W2B]; B = &sm[B2B]; h = &sm[HA2 + site * 16]; dst = HB2 + site * 32 + n; }
        float acc = B[n];
        #pragma unroll
        for (int k = 0; k < 16; k++) acc += h[k] * W[k * 32 + n];
        sm[dst] = fmaxf(acc, 0.f);
    }
    __syncthreads();

    // ---- Phase C: layer c (32 -> 16). 640 tasks. Writes slot X (hA dead) ----
    for (int task = tid; task < 640; task += 256) {
        int site = task >> 5;
        int n    = task & 31;
        const float *W, *B, *h; int dst;
        if (n < 16) { W = &sm[W1C]; B = &sm[B1C]; h = &sm[HB1 + site * 32]; dst = HC1 + site * 16 + n; }
        else { n -= 16; W = &sm[W2C]; B = &sm[B2C]; h = &sm[HB2 + site * 32]; dst = HC2 + site * 16 + n; }
        float acc = B[n];
        #pragma unroll
        for (int k = 0; k < 32; k++) acc += h[k] * W[k * 16 + n];
        sm[dst] = fmaxf(acc, 0.f);
    }
    __syncthreads();

    // ---- Phase D: output layer (16 -> 19 | 16 -> 186), no relu.
    //      Thread owns one output neuron; weight column cached in registers;
    //      hidden reads are warp-broadcast. Writes slot Y (hB dead). ----
    if (tid < 205) {
        float w[16];
        float bias;
        if (tid < 19) {
            #pragma unroll
            for (int k = 0; k < 16; k++) w[k] = sm[W1D + k * 19 + tid];
            bias = sm[B1D + tid];
            for (int site = 0; site < NU; site++) {
                float acc = bias;
                #pragma unroll
                for (int k = 0; k < 16; k++) acc += sm[HC1 + site * 16 + k] * w[k];
                sm[OUT1 + site * 19 + tid] = acc;
            }
        } else {
            int m = tid - 19;
            #pragma unroll
            for (int k = 0; k < 16; k++) w[k] = sm[W2D + k * 186 + m];
            bias = sm[B2D + m];
            for (int site = 0; site < NU; site++) {
                float acc = bias;
                #pragma unroll
                for (int k = 0; k < 16; k++) acc += sm[HC2 + site * 16 + k] * w[k];
                sm[OUT2 + site * 186 + m] = acc;
            }
        }
    }
    __syncthreads();

    // ---- Phase E: write all four output regions, coalesced, single pass ----
    // f1: out1[site][0]
    for (int t = tid; t < NU; t += 256)
        out[F1OFF + (size_t)b * NU + t] = sm[OUT1 + t * 19];

    // f2: out2[site][z], r = site*6+z
    for (int t = tid; t < NCOL; t += 256) {
        int site = t / DZ, z = t - site * DZ;
        out[F2OFF + (size_t)b * NCOL + t] = sm[OUT2 + site * 186 + z];
    }

    // g1: (20 x 120), band of 18 starting at ((i-1)*6 mod 120), vals out1[i][1+j]
    {
        float4* g1p = reinterpret_cast<float4*>(out + G1OFF + (size_t)b * (NU * NCOL));
        for (int q = tid; q < 600; q += 256) {
            int i  = q / 30;
            int c0 = (q - i * 30) * 4;
            int cs = ((i + 19) % NU) * DZ;
            float vv[4];
            #pragma unroll
            for (int t = 0; t < 4; t++) {
                int j = c0 + t - cs;
                if (j < 0) j += NCOL;
                vv[t] = (j < 18) ? sm[OUT1 + i * 19 + 1 + j] : 0.f;
            }
            g1p[q] = make_float4(vv[0], vv[1], vv[2], vv[3]);
        }
    }

    // g2: (120 x 120), band of 30 starting at ((site-2)*6 mod 120),
    //     vals out2[site][6 + z*30 + j], r = site*6+z
    {
        float4* g2p = reinterpret_cast<float4*>(out + G2OFF + (size_t)b * (NCOL * NCOL));
        for (int q = tid; q < 3600; q += 256) {
            int r    = q / 30;
            int c0   = (q - r * 30) * 4;
            int site = r / DZ;
            int z    = r - site * DZ;
            int cs   = ((site + 18) % NU) * DZ;
            const float* src = &sm[OUT2 + site * 186 + 6 + z * 30];
            float vv[4];
            #pragma unroll
            for (int t = 0; t < 4; t++) {
                int j = c0 + t - cs;
                if (j < 0) j += NCOL;
                vv[t] = (j < 30) ? src[j] : 0.f;
            }
            g2p[q] = make_float4(vv[0], vv[1], vv[2], vv[3]);
        }
    }
}

extern "C" void kernel_launch(void* const* d_in, const int* in_sizes, int n_in,
                              void* d_out, int out_size) {
    const float* x   = (const float*)d_in[0];
    const float* w1a = (const float*)d_in[1];
    const float* b1a = (const float*)d_in[2];
    const float* w1b = (const float*)d_in[3];
    const float* b1b = (const float*)d_in[4];
    const float* w1c = (const float*)d_in[5];
    const float* b1c = (const float*)d_in[6];
    const float* w1d = (const float*)d_in[7];
    const float* b1d = (const float*)d_in[8];
    const float* w2a = (const float*)d_in[9];
    const float* b2a = (const float*)d_in[10];
    const float* w2b = (const float*)d_in[11];
    const float* b2b = (const float*)d_in[12];
    const float* w2c = (const float*)d_in[13];
    const float* b2c = (const float*)d_in[14];
    const float* w2d = (const float*)d_in[15];
    const float* b2d = (const float*)d_in[16];

    CGN_fused_kernel<<<BATCH, 256>>>(
        x, w1a, b1a, w1b, b1b, w1c, b1c, w1d, b1d,
        w2a, b2a, w2b, b2b, w2c, b2c, w2d, b2d,
        (float*)d_out);
}

// round 4
// speedup vs baseline: 1.3441x; 1.3441x over previous
#include <cuda_runtime.h>

#define BATCH 4096
#define NU    20
#define DZ    6
#define NCOL  120

// Output regions (floats): f1 | g1 | f2 | g2
#define F1OFF 0
#define G1OFF (BATCH * NU)
#define F2OFF (G1OFF + BATCH * NU * NCOL)
#define G2OFF (F2OFF + BATCH * NCOL)

// Shared-memory float offsets (all buffers 16B-aligned)
#define W1A 0
#define B1A 48
#define W1B 64
#define B1B 576
#define W1C 608
#define B1C 1120
#define W2A 1136
#define B2A 1184
#define W2B 1200
#define B2B 1712
#define W2C 1744
#define B2C 2256
#define SX  2272
#define HA1 2292        /* 20*16 */
#define HA2 2628        /* +336 pad => bank-disjoint halves */
#define HC1 HA1
#define HC2 HA2
#define HB1 2948        /* 20*32 */
#define HB2 3588
#define SMEM_FLOATS 4228

__global__ __launch_bounds__(256) void CGN_fused_kernel(
    const float* __restrict__ x,
    const float* __restrict__ w1a, const float* __restrict__ bb1a,
    const float* __restrict__ w1b, const float* __restrict__ bb1b,
    const float* __restrict__ w1c, const float* __restrict__ bb1c,
    const float* __restrict__ w1d, const float* __restrict__ bb1d,
    const float* __restrict__ w2a, const float* __restrict__ bb2a,
    const float* __restrict__ w2b, const float* __restrict__ bb2b,
    const float* __restrict__ w2c, const float* __restrict__ bb2c,
    const float* __restrict__ w2d, const float* __restrict__ bb2d,
    float* __restrict__ out)
{
    __shared__ float sm[SMEM_FLOATS];
    const int tid = threadIdx.x;
    const int b   = blockIdx.x;

    float* g1o = out + G1OFF + (size_t)b * (NU * NCOL);
    float* g2o = out + G2OFF + (size_t)b * (NCOL * NCOL);

    // ---- Phase Z: zero-fill g1 & g2 with pure wide stores ----
    {
        const float4 z4 = make_float4(0.f, 0.f, 0.f, 0.f);
        float4* p1 = reinterpret_cast<float4*>(g1o);
        for (int q = tid; q < 600; q += 256) p1[q] = z4;
        float4* p2 = reinterpret_cast<float4*>(g2o);
        for (int q = tid; q < 3600; q += 256) p2[q] = z4;
    }

    // ---- stage abc-layer weights + x row into smem ----
    #define CP(off, src, n) for (int i = tid; i < (n); i += 256) sm[(off) + i] = (src)[i];
    CP(W1A, w1a, 48)   CP(B1A, bb1a, 16)
    CP(W1B, w1b, 512)  CP(B1B, bb1b, 32)
    CP(W1C, w1c, 512)  CP(B1C, bb1c, 16)
    CP(W2A, w2a, 48)   CP(B2A, bb2a, 16)
    CP(W2B, w2b, 512)  CP(B2B, bb2b, 32)
    CP(W2C, w2c, 512)  CP(B2C, bb2c, 16)
    #undef CP
    for (int i = tid; i < NU; i += 256) sm[SX + i] = x[(size_t)b * NU + i];
    __syncthreads();

    // ---- Phase A: layer a (3 -> 16), both MLPs, 20 sites. 640 tasks ----
    for (int task = tid; task < 640; task += 256) {
        int site = task >> 5;
        int n    = task & 31;
        float x0 = sm[SX + (site + 19) % NU];
        float x1 = sm[SX + site];
        float x2 = sm[SX + (site + 1) % NU];
        bool m1 = n < 16;
        int  nn = m1 ? n : n - 16;
        const float* W = m1 ? &sm[W1A] : &sm[W2A];
        float bias     = m1 ? sm[B1A + nn] : sm[B2A + nn];
        float acc = bias + x0 * W[nn] + x1 * W[16 + nn] + x2 * W[32 + nn];
        sm[(m1 ? HA1 : HA2) + site * 16 + nn] = fmaxf(acc, 0.f);
    }
    __syncthreads();

    // ---- Phase B: layer b (16 -> 32). Exactly 256 tasks: 64 neurons x 4 site-groups.
    //      Weight column cached in regs; h read as float4 broadcasts. ----
    {
        int n  = tid & 63;
        int sg = tid >> 6;
        bool m1 = n < 32;
        int  nn = n & 31;
        const float* W = m1 ? &sm[W1B] : &sm[W2B];
        float bias     = m1 ? sm[B1B + nn] : sm[B2B + nn];
        float w[16];
        #pragma unroll
        for (int k = 0; k < 16; k++) w[k] = W[k * 32 + nn];
        int ha = m1 ? HA1 : HA2;
        int hb = m1 ? HB1 : HB2;
        #pragma unroll
        for (int s5 = 0; s5 < 5; s5++) {
            int s = sg * 5 + s5;
            const float4* h4 = reinterpret_cast<const float4*>(&sm[ha + s * 16]);
            float4 h0 = h4[0], h1 = h4[1], h2 = h4[2], h3 = h4[3];
            float acc = bias;
            acc += h0.x * w[0]  + h0.y * w[1]  + h0.z * w[2]  + h0.w * w[3];
            acc += h1.x * w[4]  + h1.y * w[5]  + h1.z * w[6]  + h1.w * w[7];
            acc += h2.x * w[8]  + h2.y * w[9]  + h2.z * w[10] + h2.w * w[11];
            acc += h3.x * w[12] + h3.y * w[13] + h3.z * w[14] + h3.w * w[15];
            sm[hb + s * 32 + nn] = fmaxf(acc, 0.f);
        }
    }
    __syncthreads();

    // ---- Phase C: layer c (32 -> 16). 640 tasks, float4 h reads ----
    for (int task = tid; task < 640; task += 256) {
        int site = task >> 5;
        int n    = task & 31;
        bool m1 = n < 16;
        int  nn = m1 ? n : n - 16;
        const float* W = m1 ? &sm[W1C] : &sm[W2C];
        float acc      = m1 ? sm[B1C + nn] : sm[B2C + nn];
        const float4* h4 = reinterpret_cast<const float4*>(&sm[(m1 ? HB1 : HB2) + site * 32]);
        #pragma unroll
        for (int k8 = 0; k8 < 8; k8++) {
            float4 h = h4[k8];
            acc += h.x * W[(4 * k8 + 0) * 16 + nn];
            acc += h.y * W[(4 * k8 + 1) * 16 + nn];
            acc += h.z * W[(4 * k8 + 2) * 16 + nn];
            acc += h.w * W[(4 * k8 + 3) * 16 + nn];
        }
        sm[(m1 ? HC1 : HC2) + site * 16 + nn] = fmaxf(acc, 0.f);
    }
    __syncthreads();

    // ---- Phase D: output layer fused with banded scatter.
    //      820 task-groups = 205 neurons x 4 site-groups (5 sites each).
    //      Weight columns read from global (L1-resident), results stored
    //      directly to final positions (consecutive neurons -> consecutive
    //      columns -> coalesced). Zero-filled background already written. ----
    for (int g = tid; g < 820; g += 256) {
        int nrn = g % 205;
        int sg  = g / 205;
        bool is1 = nrn < 19;
        float w[16], bias;
        int m = 0, zq = 0, jq = 0;
        if (is1) {
            #pragma unroll
            for (int k = 0; k < 16; k++) w[k] = w1d[k * 19 + nrn];
            bias = bb1d[nrn];
        } else {
            m = nrn - 19;
            #pragma unroll
            for (int k = 0; k < 16; k++) w[k] = w2d[k * 186 + m];
            bias = bb2d[m];
            if (m >= 6) { zq = (m - 6) / 30; jq = (m - 6) % 30; }
        }
        int hc = is1 ? HC1 : HC2;
        #pragma unroll
        for (int s5 = 0; s5 < 5; s5++) {
            int s = sg * 5 + s5;
            const float4* h4 = reinterpret_cast<const float4*>(&sm[hc + s * 16]);
            float4 h0 = h4[0], h1 = h4[1], h2 = h4[2], h3 = h4[3];
            float acc = bias;
            acc += h0.x * w[0]  + h0.y * w[1]  + h0.z * w[2]  + h0.w * w[3];
            acc += h1.x * w[4]  + h1.y * w[5]  + h1.z * w[6]  + h1.w * w[7];
            acc += h2.x * w[8]  + h2.y * w[9]  + h2.z * w[10] + h2.w * w[11];
            acc += h3.x * w[12] + h3.y * w[13] + h3.z * w[14] + h3.w * w[15];

            if (is1) {
                if (nrn == 0) {
                    out[F1OFF + (size_t)b * NU + s] = acc;
                } else {
                    int cs  = ((s + 19) % 20) * 6;
                    int col = cs + (nrn - 1);
                    if (col >= 120) col -= 120;
                    g1o[s * 120 + col] = acc;
                }
            } else if (m < 6) {
                out[F2OFF + (size_t)b * NCOL + s * 6 + m] = acc;
            } else {
                int cs  = ((s + 18) % 20) * 6;
                int col = cs + jq;
                if (col >= 120) col -= 120;
                g2o[(s * 6 + zq) * 120 + col] = acc;
            }
        }
    }
}

extern "C" void kernel_launch(void* const* d_in, const int* in_sizes, int n_in,
                              void* d_out, int out_size) {
    const float* x   = (const float*)d_in[0];
    const float* w1a = (const float*)d_in[1];
    const float* b1a = (const float*)d_in[2];
    const float* w1b = (const float*)d_in[3];
    const float* b1b = (const float*)d_in[4];
    const float* w1c = (const float*)d_in[5];
    const float* b1c = (const float*)d_in[6];
    const float* w1d = (const float*)d_in[7];
    const float* b1d = (const float*)d_in[8];
    const float* w2a = (const float*)d_in[9];
    const float* b2a = (const float*)d_in[10];
    const float* w2b = (const float*)d_in[11];
    const float* b2b = (const float*)d_in[12];
    const float* w2c = (const float*)d_in[13];
    const float* b2c = (const float*)d_in[14];
    const float* w2d = (const float*)d_in[15];
    const float* b2d = (const float*)d_in[16];

    CGN_fused_kernel<<<BATCH, 256>>>(
        x, w1a, b1a, w1b, b1b, w1c, b1c, w1d, b1d,
        w2a, b2a, w2b, b2b, w2c, b2c, w2d, b2d,
        (float*)d_out);
}